// round 2
// baseline (speedup 1.0000x reference)
#include <cuda_runtime.h>
#include <math.h>

namespace {
constexpr int B_ = 8, L_ = 256, H_ = 256, NH = 4, D_ = 64, NBLK = 2;
constexpr int ROWS = B_ * L_;          // 2048
}
#define BIGNEG (-4294967295.0f)

// ---- scratch (allocation-free: __device__ globals) ----
__device__ float g_x[ROWS * H_];
__device__ float g_q[ROWS * H_];
__device__ float g_Q[ROWS * H_];
__device__ float g_K[ROWS * H_];
__device__ float g_V[ROWS * H_];
__device__ float g_att[ROWS * H_];
__device__ float g_xa[ROWS * H_];
__device__ float g_h[ROWS * H_];
__device__ float g_P[B_ * NH * L_ * L_];   // 8 MB attention probs
__device__ unsigned char g_mask[ROWS];

// ---- mask dtype sniffer + converter (single block) ----
// Reads only the first 2048 BYTES of the buffer (safe whether the buffer holds
// 2048 uint8, 2048 int32, or 2048 float32 elements). Decides layout, then
// materializes g_mask[2048] as 0/1 uint8.
__global__ void k_mask_convert(const void* __restrict__ mraw) {
    __shared__ int s_f32, s_u8;
    const unsigned int* w = (const unsigned int*)mraw;
    int t = threadIdx.x;
    if (t == 0) { s_f32 = 0; s_u8 = 0; }
    __syncthreads();
    // scan first 512 words = 2048 bytes
    for (int i = t; i < 512; i += 256) {
        unsigned int v = w[i];
        if (v == 0x3F800000u) atomicOr(&s_f32, 1);          // exact 1.0f word
        if (v & 0xFFFFFF00u)  atomicOr(&s_u8, 1);           // nonzero high bytes
    }
    __syncthreads();
    int mode = s_f32 ? 2 : (s_u8 ? 0 : 1);  // 2=f32, 0=u8, 1=i32
    const unsigned char* u8 = (const unsigned char*)mraw;
    const int* i32 = (const int*)mraw;
    const float* f32 = (const float*)mraw;
    for (int i = t; i < ROWS; i += 256) {
        unsigned char m;
        if (mode == 0)      m = u8[i] ? 1 : 0;
        else if (mode == 1) m = i32[i] ? 1 : 0;
        else                m = (f32[i] != 0.f) ? 1 : 0;
        g_mask[i] = m;
    }
}

// x = seq_emb * keep
__global__ void k_maskmul(const float* __restrict__ e) {
    int i = blockIdx.x * blockDim.x + threadIdx.x;
    int row = i >> 8;
    g_x[i] = g_mask[row] ? 0.f : e[i];
}

// out = LN(in1 (+ in2)) * g + b   (eps=1e-8, biased var)
__global__ void k_ln(const float* __restrict__ in1, const float* __restrict__ in2,
                     const float* __restrict__ gg, const float* __restrict__ bb,
                     float* __restrict__ out) {
    int row = blockIdx.x, t = threadIdx.x;
    float v = in1[row * H_ + t];
    if (in2) v += in2[row * H_ + t];
    __shared__ float r1[8], r2[8];
    __shared__ float mean_s, inv_s;
    float s = v;
    #pragma unroll
    for (int o = 16; o; o >>= 1) s += __shfl_xor_sync(~0u, s, o);
    if ((t & 31) == 0) r1[t >> 5] = s;
    __syncthreads();
    if (t == 0) {
        float tot = 0.f;
        #pragma unroll
        for (int i = 0; i < 8; i++) tot += r1[i];
        mean_s = tot * (1.f / H_);
    }
    __syncthreads();
    float m = mean_s;
    float dv = v - m;
    float sq = dv * dv;
    #pragma unroll
    for (int o = 16; o; o >>= 1) sq += __shfl_xor_sync(~0u, sq, o);
    if ((t & 31) == 0) r2[t >> 5] = sq;
    __syncthreads();
    if (t == 0) {
        float tot = 0.f;
        #pragma unroll
        for (int i = 0; i < 8; i++) tot += r2[i];
        inv_s = rsqrtf(tot * (1.f / H_) + 1e-8f);
    }
    __syncthreads();
    out[row * H_ + t] = dv * inv_s * gg[t] + bb[t];
}

// C[i,o] = sum_d A[i,d]*W[o,d] + bias[o]  (+relu | +res,*keep)
// mode: 0 = plain, 1 = relu, 2 = +res then *keep
__global__ void k_gemm(const float* __restrict__ A, const float* __restrict__ W,
                       const float* __restrict__ bias, const float* __restrict__ res,
                       float* __restrict__ C, int mode) {
    __shared__ float As[32][33], Ws[32][33];
    int tx = threadIdx.x, ty = threadIdx.y;
    int o0 = blockIdx.x * 32, i0 = blockIdx.y * 32;
    float acc = 0.f;
    for (int kt = 0; kt < H_; kt += 32) {
        As[ty][tx] = A[(i0 + ty) * H_ + kt + tx];
        Ws[ty][tx] = W[(o0 + ty) * H_ + kt + tx];
        __syncthreads();
        #pragma unroll
        for (int k = 0; k < 32; k++) acc += As[ty][k] * Ws[tx][k];
        __syncthreads();
    }
    int row = i0 + ty, o = o0 + tx;
    acc += bias[o];
    if (mode == 1) {
        acc = fmaxf(acc, 0.f);
    } else if (mode == 2) {
        acc += res[row * H_ + o];
        if (g_mask[row]) acc = 0.f;
    }
    C[row * H_ + o] = acc;
}

// scores + softmax -> g_P.  block per (b,q), warp per head.
__global__ void k_attn_score(const int* __restrict__ tm,
                             const float* __restrict__ posK,
                             const float* __restrict__ tK) {
    int bq = blockIdx.x;
    int b = bq >> 8, q = bq & 255;
    int w = threadIdx.x >> 5, lane = threadIdx.x & 31;
    __shared__ float Qs[H_];
    __shared__ float S[NH][L_];
    Qs[threadIdx.x] = g_Q[bq * H_ + threadIdx.x];
    Qs[threadIdx.x + 128] = g_Q[bq * H_ + threadIdx.x + 128];
    for (int k = lane; k < L_; k += 32) S[w][k] = BIGNEG;
    __syncthreads();
    bool mq = g_mask[bq] != 0;
    int hd = w * D_;
    const int* tmr = tm + (long)bq * L_;
    float q0 = Qs[hd + lane], q1 = Qs[hd + lane + 32];
    if (!mq) {
        for (int k = 0; k <= q; k++) {
            int t = tmr[k];
            const float* Kr = g_K + (b * L_ + k) * H_ + hd;
            const float* pr = posK + k * H_ + hd;
            const float* tr = tK + t * H_ + hd;
            float s = q0 * (Kr[lane] + pr[lane] + tr[lane]);
            int d2 = lane + 32;
            s += q1 * (Kr[d2] + pr[d2] + tr[d2]);
            #pragma unroll
            for (int o = 16; o; o >>= 1) s += __shfl_xor_sync(~0u, s, o);
            if (lane == 0) S[w][k] = s * 0.125f;   // / sqrt(64)
        }
    }
    __syncwarp();
    // softmax over 256 keys (8 per lane). All-BIGNEG row -> uniform 1/256
    float e[8];
    float mx = BIGNEG;
    #pragma unroll
    for (int j = 0; j < 8; j++) { e[j] = S[w][lane + 32 * j]; mx = fmaxf(mx, e[j]); }
    #pragma unroll
    for (int o = 16; o; o >>= 1) mx = fmaxf(mx, __shfl_xor_sync(~0u, mx, o));
    float sum = 0.f;
    #pragma unroll
    for (int j = 0; j < 8; j++) { e[j] = __expf(e[j] - mx); sum += e[j]; }
    #pragma unroll
    for (int o = 16; o; o >>= 1) sum += __shfl_xor_sync(~0u, sum, o);
    float inv = 1.f / sum;
    float* Pr = g_P + (((long)(b * NH + w) * L_ + q) * L_);
    #pragma unroll
    for (int j = 0; j < 8; j++) Pr[lane + 32 * j] = e[j] * inv;
}

// out[b,q,:] = sum_k p * (V + posV + tV).  block per (b,q), thread per dim.
__global__ void k_attn_out(const int* __restrict__ tm,
                           const float* __restrict__ posV,
                           const float* __restrict__ tV) {
    int bq = blockIdx.x;
    int b = bq >> 8, q = bq & 255;
    int d = threadIdx.x, h = d >> 6;
    __shared__ float ps[NH][L_];
    __shared__ int ts[L_];
    #pragma unroll
    for (int j = 0; j < NH; j++)
        ps[j][d] = g_P[(((long)(b * NH + j) * L_ + q) * L_) + d];
    ts[d] = tm[(long)bq * L_ + d];
    __syncthreads();
    bool mq = g_mask[bq] != 0;
    int kmax = mq ? (L_ - 1) : q;   // masked query: uniform attn over ALL keys
    float acc = 0.f;
    for (int k = 0; k <= kmax; k++) {
        float p = ps[h][k];
        acc += p * (g_V[(b * L_ + k) * H_ + d] + posV[k * H_ + d] + tV[ts[k] * H_ + d]);
    }
    g_att[bq * H_ + d] = acc;
}

extern "C" void kernel_launch(void* const* d_in, const int* in_sizes, int n_in,
                              void* d_out, int out_size) {
    const void*  mraw = d_in[0];
    const float* seq  = (const float*)d_in[1];
    const int*   tm   = (const int*)d_in[3];
    // If the scalar time_attn (index 4, 1 element) is present, weights start at 5.
    int base = (n_in >= 25 && in_sizes[4] == 1) ? 5 : 4;
    const float* Wq   = (const float*)d_in[base + 0];  const float* bq  = (const float*)d_in[base + 1];
    const float* Wk   = (const float*)d_in[base + 2];  const float* bk  = (const float*)d_in[base + 3];
    const float* Wv   = (const float*)d_in[base + 4];  const float* bv  = (const float*)d_in[base + 5];
    const float* ln1g = (const float*)d_in[base + 6];  const float* ln1b = (const float*)d_in[base + 7];
    const float* ln2g = (const float*)d_in[base + 8];  const float* ln2b = (const float*)d_in[base + 9];
    const float* W1   = (const float*)d_in[base + 10]; const float* b1  = (const float*)d_in[base + 11];
    const float* W2   = (const float*)d_in[base + 12]; const float* b2  = (const float*)d_in[base + 13];
    const float* posK = (const float*)d_in[base + 14]; const float* posV = (const float*)d_in[base + 15];
    const float* tK   = (const float*)d_in[base + 16]; const float* tV  = (const float*)d_in[base + 17];
    const float* lnfg = (const float*)d_in[base + 18]; const float* lnfb = (const float*)d_in[base + 19];
    float* out = (float*)d_out;

    float *px, *pq, *pQ, *pK, *pV, *patt, *pxa, *ph;
    cudaGetSymbolAddress((void**)&px,  g_x);
    cudaGetSymbolAddress((void**)&pq,  g_q);
    cudaGetSymbolAddress((void**)&pQ,  g_Q);
    cudaGetSymbolAddress((void**)&pK,  g_K);
    cudaGetSymbolAddress((void**)&pV,  g_V);
    cudaGetSymbolAddress((void**)&patt, g_att);
    cudaGetSymbolAddress((void**)&pxa, g_xa);
    cudaGetSymbolAddress((void**)&ph,  g_h);

    dim3 gb(32, 32), gg(H_ / 32, ROWS / 32);

    k_mask_convert<<<1, 256>>>(mraw);
    k_maskmul<<<ROWS * H_ / 256, 256>>>(seq);
    for (int i = 0; i < NBLK; i++) {
        const float* wq = Wq + (long)i * H_ * H_;
        const float* wk = Wk + (long)i * H_ * H_;
        const float* wv = Wv + (long)i * H_ * H_;
        const float* w1 = W1 + (long)i * H_ * H_;
        const float* w2 = W2 + (long)i * H_ * H_;
        k_ln<<<ROWS, 256>>>(px, nullptr, ln1g + i * H_, ln1b + i * H_, pq);
        k_gemm<<<gg, gb>>>(pq, wq, bq + i * H_, nullptr, pQ, 0);
        k_gemm<<<gg, gb>>>(px, wk, bk + i * H_, nullptr, pK, 0);
        k_gemm<<<gg, gb>>>(px, wv, bv + i * H_, nullptr, pV, 0);
        k_attn_score<<<ROWS, 128>>>(tm, posK, tK);
        k_attn_out<<<ROWS, 256>>>(tm, posV, tV);
        k_ln<<<ROWS, 256>>>(pq, patt, ln2g + i * H_, ln2b + i * H_, pxa);
        k_gemm<<<gg, gb>>>(pxa, w1, b1 + i * H_, nullptr, ph, 1);
        k_gemm<<<gg, gb>>>(ph, w2, b2 + i * H_, pxa, px, 2);
    }
    k_ln<<<ROWS, 256>>>(px, nullptr, lnfg, lnfb, out);
}

// round 3
// speedup vs baseline: 1.6868x; 1.6868x over previous
#include <cuda_runtime.h>
#include <math.h>

namespace {
constexpr int B_ = 8, L_ = 256, H_ = 256, NH = 4, D_ = 64, NBLK = 2;
constexpr int ROWS = B_ * L_;          // 2048
}
#define BIGNEG (-4294967295.0f)

// ---- scratch (allocation-free: __device__ globals) ----
__device__ float g_x[ROWS * H_];
__device__ float g_q[ROWS * H_];
__device__ float g_Q[ROWS * H_];
__device__ float g_K[ROWS * H_];
__device__ float g_V[ROWS * H_];
__device__ float g_att[ROWS * H_];
__device__ float g_xa[ROWS * H_];
__device__ float g_h[ROWS * H_];
__device__ float g_P[B_ * NH * L_ * L_];   // 8 MB attention probs
__device__ unsigned char g_mask[ROWS];

// ---- mask dtype sniffer + converter (single block) ----
__global__ void k_mask_convert(const void* __restrict__ mraw) {
    __shared__ int s_f32, s_u8;
    const unsigned int* w = (const unsigned int*)mraw;
    int t = threadIdx.x;
    if (t == 0) { s_f32 = 0; s_u8 = 0; }
    __syncthreads();
    for (int i = t; i < 512; i += 256) {
        unsigned int v = w[i];
        if (v == 0x3F800000u) atomicOr(&s_f32, 1);
        if (v & 0xFFFFFF00u)  atomicOr(&s_u8, 1);
    }
    __syncthreads();
    int mode = s_f32 ? 2 : (s_u8 ? 0 : 1);  // 2=f32, 0=u8, 1=i32
    const unsigned char* u8 = (const unsigned char*)mraw;
    const int* i32 = (const int*)mraw;
    const float* f32 = (const float*)mraw;
    for (int i = t; i < ROWS; i += 256) {
        unsigned char m;
        if (mode == 0)      m = u8[i] ? 1 : 0;
        else if (mode == 1) m = i32[i] ? 1 : 0;
        else                m = (f32[i] != 0.f) ? 1 : 0;
        g_mask[i] = m;
    }
}

// x = seq_emb * keep
__global__ void k_maskmul(const float* __restrict__ e) {
    int i = blockIdx.x * blockDim.x + threadIdx.x;
    int row = i >> 8;
    g_x[i] = g_mask[row] ? 0.f : e[i];
}

// KV[b,k,d] += pos[k,d]   (broadcast over b)
__global__ void k_addpos(float* __restrict__ kv, const float* __restrict__ pos) {
    int i = blockIdx.x * blockDim.x + threadIdx.x;
    int k = (i >> 8) & 255, d = i & 255;
    kv[i] += pos[(k << 8) | d];
}

// out = LN(in1 (+ in2)) * g + b   (eps=1e-8, biased var)
__global__ void k_ln(const float* __restrict__ in1, const float* __restrict__ in2,
                     const float* __restrict__ gg, const float* __restrict__ bb,
                     float* __restrict__ out) {
    int row = blockIdx.x, t = threadIdx.x;
    float v = in1[row * H_ + t];
    if (in2) v += in2[row * H_ + t];
    __shared__ float r1[8], r2[8];
    __shared__ float mean_s, inv_s;
    float s = v;
    #pragma unroll
    for (int o = 16; o; o >>= 1) s += __shfl_xor_sync(~0u, s, o);
    if ((t & 31) == 0) r1[t >> 5] = s;
    __syncthreads();
    if (t == 0) {
        float tot = 0.f;
        #pragma unroll
        for (int i = 0; i < 8; i++) tot += r1[i];
        mean_s = tot * (1.f / H_);
    }
    __syncthreads();
    float m = mean_s;
    float dv = v - m;
    float sq = dv * dv;
    #pragma unroll
    for (int o = 16; o; o >>= 1) sq += __shfl_xor_sync(~0u, sq, o);
    if ((t & 31) == 0) r2[t >> 5] = sq;
    __syncthreads();
    if (t == 0) {
        float tot = 0.f;
        #pragma unroll
        for (int i = 0; i < 8; i++) tot += r2[i];
        inv_s = rsqrtf(tot * (1.f / H_) + 1e-8f);
    }
    __syncthreads();
    out[row * H_ + t] = dv * inv_s * gg[t] + bb[t];
}

// C[i,o] = sum_d A[i,d]*W[o,d] + bias[o]  (+relu | +res,*keep)
// 64x64 tile, BK=16, 256 threads, 4x4 outputs per thread.
__global__ __launch_bounds__(256) void k_gemm(
        const float* __restrict__ A, const float* __restrict__ W,
        const float* __restrict__ bias, const float* __restrict__ res,
        float* __restrict__ C, int mode) {
    __shared__ float As[16][64], Ws[16][64];
    int tid = threadIdx.x;
    int tx = tid & 15, ty = tid >> 4;
    int o0 = blockIdx.x * 64, i0 = blockIdx.y * 64;
    int lr = tid >> 2;            // 0..63  (tile row)
    int lc = (tid & 3) * 4;       // 0,4,8,12 (k-col group)
    float acc[4][4] = {};
    for (int kt = 0; kt < H_; kt += 16) {
        float4 av = *(const float4*)(A + (i0 + lr) * H_ + kt + lc);
        float4 wv = *(const float4*)(W + (o0 + lr) * H_ + kt + lc);
        As[lc + 0][lr] = av.x; As[lc + 1][lr] = av.y;
        As[lc + 2][lr] = av.z; As[lc + 3][lr] = av.w;
        Ws[lc + 0][lr] = wv.x; Ws[lc + 1][lr] = wv.y;
        Ws[lc + 2][lr] = wv.z; Ws[lc + 3][lr] = wv.w;
        __syncthreads();
        #pragma unroll
        for (int kk = 0; kk < 16; kk++) {
            float4 a = *(const float4*)&As[kk][ty * 4];
            float4 b = *(const float4*)&Ws[kk][tx * 4];
            acc[0][0] += a.x * b.x; acc[0][1] += a.x * b.y; acc[0][2] += a.x * b.z; acc[0][3] += a.x * b.w;
            acc[1][0] += a.y * b.x; acc[1][1] += a.y * b.y; acc[1][2] += a.y * b.z; acc[1][3] += a.y * b.w;
            acc[2][0] += a.z * b.x; acc[2][1] += a.z * b.y; acc[2][2] += a.z * b.z; acc[2][3] += a.z * b.w;
            acc[3][0] += a.w * b.x; acc[3][1] += a.w * b.y; acc[3][2] += a.w * b.z; acc[3][3] += a.w * b.w;
        }
        __syncthreads();
    }
    float4 bv = *(const float4*)(bias + o0 + tx * 4);
    #pragma unroll
    for (int i = 0; i < 4; i++) {
        int row = i0 + ty * 4 + i;
        int o = o0 + tx * 4;
        float4 r = make_float4(acc[i][0] + bv.x, acc[i][1] + bv.y,
                               acc[i][2] + bv.z, acc[i][3] + bv.w);
        if (mode == 1) {
            r.x = fmaxf(r.x, 0.f); r.y = fmaxf(r.y, 0.f);
            r.z = fmaxf(r.z, 0.f); r.w = fmaxf(r.w, 0.f);
        } else if (mode == 2) {
            float4 rv = *(const float4*)(res + row * H_ + o);
            r.x += rv.x; r.y += rv.y; r.z += rv.z; r.w += rv.w;
            if (g_mask[row]) r = make_float4(0.f, 0.f, 0.f, 0.f);
        }
        *(float4*)(C + row * H_ + o) = r;
    }
}

// scores + softmax -> g_P.  block per (b,q), warp per head. K already holds K+posK.
__global__ void k_attn_score(const int* __restrict__ tm,
                             const float* __restrict__ tK) {
    int bq = blockIdx.x;
    int b = bq >> 8, q = bq & 255;
    int w = threadIdx.x >> 5, lane = threadIdx.x & 31;
    __shared__ float Qs[H_];
    __shared__ float S[NH][L_];
    Qs[threadIdx.x] = g_Q[bq * H_ + threadIdx.x];
    Qs[threadIdx.x + 128] = g_Q[bq * H_ + threadIdx.x + 128];
    for (int k = lane; k < L_; k += 32) S[w][k] = BIGNEG;
    __syncthreads();
    bool mq = g_mask[bq] != 0;
    int hd = w * D_;
    const int* tmr = tm + (long)bq * L_;
    float q0 = Qs[hd + lane], q1 = Qs[hd + lane + 32];
    if (!mq) {
        for (int k = 0; k <= q; k++) {
            int t = tmr[k];
            const float* Kr = g_K + (b * L_ + k) * H_ + hd;
            const float* tr = tK + t * H_ + hd;
            float s = q0 * (Kr[lane] + tr[lane]);
            int d2 = lane + 32;
            s += q1 * (Kr[d2] + tr[d2]);
            #pragma unroll
            for (int o = 16; o; o >>= 1) s += __shfl_xor_sync(~0u, s, o);
            if (lane == 0) S[w][k] = s * 0.125f;   // / sqrt(64)
        }
    }
    __syncwarp();
    float e[8];
    float mx = BIGNEG;
    #pragma unroll
    for (int j = 0; j < 8; j++) { e[j] = S[w][lane + 32 * j]; mx = fmaxf(mx, e[j]); }
    #pragma unroll
    for (int o = 16; o; o >>= 1) mx = fmaxf(mx, __shfl_xor_sync(~0u, mx, o));
    float sum = 0.f;
    #pragma unroll
    for (int j = 0; j < 8; j++) { e[j] = __expf(e[j] - mx); sum += e[j]; }
    #pragma unroll
    for (int o = 16; o; o >>= 1) sum += __shfl_xor_sync(~0u, sum, o);
    float inv = 1.f / sum;
    float* Pr = g_P + (((long)(b * NH + w) * L_ + q) * L_);
    #pragma unroll
    for (int j = 0; j < 8; j++) Pr[lane + 32 * j] = e[j] * inv;
}

// out[b,q,:] = sum_k p * (V(+posV) + tV).  block per (b,q), thread per dim.
__global__ void k_attn_out(const int* __restrict__ tm,
                           const float* __restrict__ tV) {
    int bq = blockIdx.x;
    int b = bq >> 8, q = bq & 255;
    int d = threadIdx.x, h = d >> 6;
    __shared__ float ps[NH][L_];
    __shared__ int ts[L_];
    #pragma unroll
    for (int j = 0; j < NH; j++)
        ps[j][d] = g_P[(((long)(b * NH + j) * L_ + q) * L_) + d];
    ts[d] = tm[(long)bq * L_ + d];
    __syncthreads();
    bool mq = g_mask[bq] != 0;
    int kmax = mq ? (L_ - 1) : q;   // masked query: uniform attn over ALL keys
    float acc = 0.f;
    for (int k = 0; k <= kmax; k++) {
        float p = ps[h][k];
        acc += p * (g_V[(b * L_ + k) * H_ + d] + tV[ts[k] * H_ + d]);
    }
    g_att[bq * H_ + d] = acc;
}

extern "C" void kernel_launch(void* const* d_in, const int* in_sizes, int n_in,
                              void* d_out, int out_size) {
    const void*  mraw = d_in[0];
    const float* seq  = (const float*)d_in[1];
    const int*   tm   = (const int*)d_in[3];
    int base = (n_in >= 25 && in_sizes[4] == 1) ? 5 : 4;
    const float* Wq   = (const float*)d_in[base + 0];  const float* bq  = (const float*)d_in[base + 1];
    const float* Wk   = (const float*)d_in[base + 2];  const float* bk  = (const float*)d_in[base + 3];
    const float* Wv   = (const float*)d_in[base + 4];  const float* bv  = (const float*)d_in[base + 5];
    const float* ln1g = (const float*)d_in[base + 6];  const float* ln1b = (const float*)d_in[base + 7];
    const float* ln2g = (const float*)d_in[base + 8];  const float* ln2b = (const float*)d_in[base + 9];
    const float* W1   = (const float*)d_in[base + 10]; const float* b1  = (const float*)d_in[base + 11];
    const float* W2   = (const float*)d_in[base + 12]; const float* b2  = (const float*)d_in[base + 13];
    const float* posK = (const float*)d_in[base + 14]; const float* posV = (const float*)d_in[base + 15];
    const float* tK   = (const float*)d_in[base + 16]; const float* tV  = (const float*)d_in[base + 17];
    const float* lnfg = (const float*)d_in[base + 18]; const float* lnfb = (const float*)d_in[base + 19];
    float* out = (float*)d_out;

    float *px, *pq, *pQ, *pK, *pV, *patt, *pxa, *ph;
    cudaGetSymbolAddress((void**)&px,  g_x);
    cudaGetSymbolAddress((void**)&pq,  g_q);
    cudaGetSymbolAddress((void**)&pQ,  g_Q);
    cudaGetSymbolAddress((void**)&pK,  g_K);
    cudaGetSymbolAddress((void**)&pV,  g_V);
    cudaGetSymbolAddress((void**)&patt, g_att);
    cudaGetSymbolAddress((void**)&pxa, g_xa);
    cudaGetSymbolAddress((void**)&ph,  g_h);

    dim3 gb(256), gg(H_ / 64, ROWS / 64);

    k_mask_convert<<<1, 256>>>(mraw);
    k_maskmul<<<ROWS * H_ / 256, 256>>>(seq);
    for (int i = 0; i < NBLK; i++) {
        const float* wq = Wq + (long)i * H_ * H_;
        const float* wk = Wk + (long)i * H_ * H_;
        const float* wv = Wv + (long)i * H_ * H_;
        const float* w1 = W1 + (long)i * H_ * H_;
        const float* w2 = W2 + (long)i * H_ * H_;
        k_ln<<<ROWS, 256>>>(px, nullptr, ln1g + i * H_, ln1b + i * H_, pq);
        k_gemm<<<gg, gb>>>(pq, wq, bq + i * H_, nullptr, pQ, 0);
        k_gemm<<<gg, gb>>>(px, wk, bk + i * H_, nullptr, pK, 0);
        k_gemm<<<gg, gb>>>(px, wv, bv + i * H_, nullptr, pV, 0);
        k_addpos<<<ROWS * H_ / 256, 256>>>(pK, posK);
        k_addpos<<<ROWS * H_ / 256, 256>>>(pV, posV);
        k_attn_score<<<ROWS, 128>>>(tm, tK);
        k_attn_out<<<ROWS, 256>>>(tm, tV);
        k_ln<<<ROWS, 256>>>(pq, patt, ln2g + i * H_, ln2b + i * H_, pxa);
        k_gemm<<<gg, gb>>>(pxa, w1, b1 + i * H_, nullptr, ph, 1);
        k_gemm<<<gg, gb>>>(ph, w2, b2 + i * H_, pxa, px, 2);
    }
    k_ln<<<ROWS, 256>>>(px, nullptr, lnfg, lnfb, out);
}